// round 2
// baseline (speedup 1.0000x reference)
#include <cuda_runtime.h>
#include <cuda_bf16.h>
#include <cstdint>

// ---------------------------------------------------------------------------
// PCA-whitening norm. x: [64,64,128,128] fp32.
//   1. gram_kernel : partial Gram + per-channel sums  (cp.async double-buffered)
//   2. reduce_kernel
//   3. eigen_kernel : 32 x (power iter + Rayleigh + deflation) -> W, off
//   4. apply_kernel : out = W @ x + off                (cp.async double-buffered)
// ---------------------------------------------------------------------------

#define CCH   64
#define HWSZ  16384
#define RS    132
#define NTILES 8192
#define G1    296
#define G2    296
#define KEIG  32
#define EPSV  1e-5f

__device__ float g_pg[G1 * 4096];
__device__ float g_ps[G1 * 64];
__device__ float g_gram[4096];
__device__ float g_S[64];
__device__ float g_W[4096];
__device__ float g_off[64];

__device__ __forceinline__ void ffma2(unsigned long long& d,
                                      unsigned long long a,
                                      unsigned long long b) {
    asm("fma.rn.f32x2 %0, %1, %2, %0;" : "+l"(d) : "l"(a), "l"(b));
}
__device__ __forceinline__ unsigned long long pack2(float s) {
    unsigned long long d;
    asm("mov.b64 %0, {%1, %1};" : "=l"(d) : "f"(s));
    return d;
}
__device__ __forceinline__ void unpack2(unsigned long long d, float& lo, float& hi) {
    asm("mov.b64 {%0, %1}, %2;" : "=f"(lo), "=f"(hi) : "l"(d));
}
__device__ __forceinline__ void cpa16(void* s, const void* g) {
    uint32_t sa = (uint32_t)__cvta_generic_to_shared(s);
    asm volatile("cp.async.cg.shared.global [%0], [%1], 16;" :: "r"(sa), "l"(g));
}
#define CP_COMMIT asm volatile("cp.async.commit_group;")
#define CP_WAIT1  asm volatile("cp.async.wait_group 1;")
#define CP_WAIT0  asm volatile("cp.async.wait_group 0;")

// ---------------------------------------------------------------------------
// Pass 1: partial Gram + channel sums. 256 threads, 2 blocks/SM.
// Tile 64ch x 128m double-buffered via cp.async. 8x4 register tile, K-step 4
// (LDS.128): 12 LDS per 64 FFMA2.
// ---------------------------------------------------------------------------
__global__ void __launch_bounds__(256, 2)
gram_kernel(const float* __restrict__ x) {
    extern __shared__ float sm[];
    float* buf0 = sm;
    float* buf1 = sm + CCH * RS;

    const int t    = threadIdx.x;
    const int g2   = t >> 7;
    const int tg   = t & 127;
    const int i    = tg >> 4;        // rows i + 8r
    const int j    = tg & 15;        // cols j + 16c
    const int wa   = t >> 5;
    const int lane = t & 31;
    const int mb   = g2 * 64;
    const int srow = t >> 2;         // csum row
    const int scol = (t & 3) * 32;   // csum col base

    unsigned long long acc[8][4];
#pragma unroll
    for (int r = 0; r < 8; r++)
#pragma unroll
        for (int c = 0; c < 4; c++) acc[r][c] = 0ULL;
    float csum = 0.0f;

    // prologue: prefetch first tile into buf0
    {
        const int tau = blockIdx.x;
        const int n = tau >> 7, m0 = (tau & 127) << 7;
        const float* base = x + (size_t)(n * CCH) * HWSZ + m0;
#pragma unroll
        for (int q = 0; q < 8; q++) {
            const int c = q * 8 + wa;
            cpa16(buf0 + c * RS + lane * 4, base + (size_t)c * HWSZ + lane * 4);
        }
    }
    CP_COMMIT;

    int parity = 0;
    for (int tau = blockIdx.x; tau < NTILES; tau += G1) {
        const int taun = tau + G1;
        float* nb = parity ? buf0 : buf1;
        if (taun < NTILES) {
            const int n = taun >> 7, m0 = (taun & 127) << 7;
            const float* base = x + (size_t)(n * CCH) * HWSZ + m0;
#pragma unroll
            for (int q = 0; q < 8; q++) {
                const int c = q * 8 + wa;
                cpa16(nb + c * RS + lane * 4, base + (size_t)c * HWSZ + lane * 4);
            }
        }
        CP_COMMIT;
        CP_WAIT1;
        __syncthreads();
        const float* tb = parity ? buf1 : buf0;

        // channel sums from smem tile: thread sums tile[srow][scol..scol+32)
        {
            float s = 0.0f;
#pragma unroll
            for (int k = 0; k < 8; k++) {
                const float4 v4 = *(const float4*)(tb + srow * RS + scol + 4 * k);
                s += (v4.x + v4.y) + (v4.z + v4.w);
            }
            csum += s;
        }

        // Gram MMA, K-step 4
#pragma unroll 2
        for (int mg = 0; mg < 16; mg++) {
            const int m = mb + 4 * mg;
            longlong2 av[8], bv[4];
#pragma unroll
            for (int r = 0; r < 8; r++)
                av[r] = *(const longlong2*)(tb + (i + 8 * r) * RS + m);
#pragma unroll
            for (int c = 0; c < 4; c++)
                bv[c] = *(const longlong2*)(tb + (j + 16 * c) * RS + m);
#pragma unroll
            for (int r = 0; r < 8; r++)
#pragma unroll
                for (int c = 0; c < 4; c++) {
                    ffma2(acc[r][c], (unsigned long long)av[r].x,
                                      (unsigned long long)bv[c].x);
                    ffma2(acc[r][c], (unsigned long long)av[r].y,
                                      (unsigned long long)bv[c].y);
                }
        }
        __syncthreads();
        parity ^= 1;
    }

    // channel-sum reduce: lanes 4r..4r+3 share row srow
    csum += __shfl_down_sync(0xffffffffu, csum, 2);
    csum += __shfl_down_sync(0xffffffffu, csum, 1);
    if ((t & 3) == 0) g_ps[blockIdx.x * 64 + srow] = csum;

    // combine the two m-halves in smem (buf0), then write partial gram
    if (g2 == 0) {
#pragma unroll
        for (int r = 0; r < 8; r++)
#pragma unroll
            for (int c = 0; c < 4; c++) {
                float lo, hi; unpack2(acc[r][c], lo, hi);
                buf0[(i + 8 * r) * 65 + (j + 16 * c)] = lo + hi;
            }
    }
    __syncthreads();
    if (g2 == 1) {
#pragma unroll
        for (int r = 0; r < 8; r++)
#pragma unroll
            for (int c = 0; c < 4; c++) {
                float lo, hi; unpack2(acc[r][c], lo, hi);
                buf0[(i + 8 * r) * 65 + (j + 16 * c)] += lo + hi;
            }
    }
    __syncthreads();
    float* pg = g_pg + (size_t)blockIdx.x * 4096;
#pragma unroll
    for (int kk = 0; kk < 16; kk++) {
        const int idx = t + kk * 256;
        pg[idx] = buf0[(idx >> 6) * 65 + (idx & 63)];
    }
}

// ---------------------------------------------------------------------------
__global__ void reduce_kernel() {
    const int b = blockIdx.x, t = threadIdx.x;
    if (b < 64) {
        const int idx = b * 64 + t;
        float s = 0.0f;
        for (int g = 0; g < G1; g++) s += g_pg[g * 4096 + idx];
        g_gram[idx] = s;
    } else {
        float s = 0.0f;
        for (int g = 0; g < G1; g++) s += g_ps[g * 64 + t];
        g_S[t] = s;
    }
}

// ---------------------------------------------------------------------------
// Eigen kernel: single block, 256 threads.
// ---------------------------------------------------------------------------
__global__ void eigen_kernel(const float* __restrict__ weight,
                             const float* __restrict__ bias,
                             const float* __restrict__ vinit) {
    __shared__ float cov[64 * 65];
    __shared__ float v[64];
    __shared__ float wv[64];
    __shared__ float red[256];
    __shared__ float mu[64];
    __shared__ float Vs[KEIG * 64];
    __shared__ float lamArr[KEIG];
    __shared__ float invs[KEIG];
    __shared__ float scal;

    const int t = threadIdx.x;
    const float invM = 1.0f / 1048576.0f;

    if (t < 64) mu[t] = g_S[t] * invM;
    __syncthreads();
    for (int idx = t; idx < 4096; idx += 256) {
        const int ii = idx >> 6, jj = idx & 63;
        float c = g_gram[idx] * invM - mu[ii] * mu[jj];
        if (ii == jj) c += EPSV;
        cov[ii * 65 + jj] = c;
    }
    const int row = t & 63, part = t >> 6;
    __syncthreads();

    for (int k = 0; k < KEIG; k++) {
        if (t < 64) v[t] = vinit[k * 64 + t];
        __syncthreads();
        for (int it = 0; it < 10; it++) {
            float p = 0.0f;
#pragma unroll
            for (int q = 0; q < 16; q++)
                p += cov[row * 65 + part * 16 + q] * v[part * 16 + q];
            red[part * 64 + row] = p;
            __syncthreads();
            if (part == 0)
                v[row] = (red[row] + red[64 + row]) + (red[128 + row] + red[192 + row]);
            __syncthreads();
        }
        if (t < 64) red[t] = v[t] * v[t];
        __syncthreads();
        if (t < 32) {
            float s = red[t] + red[t + 32];
#pragma unroll
            for (int off = 16; off > 0; off >>= 1)
                s += __shfl_down_sync(0xffffffffu, s, off);
            if (t == 0) scal = 1.0f / sqrtf(s);
        }
        __syncthreads();
        if (t < 64) v[t] *= scal;
        __syncthreads();
        {
            float p = 0.0f;
#pragma unroll
            for (int q = 0; q < 16; q++)
                p += cov[row * 65 + part * 16 + q] * v[part * 16 + q];
            red[part * 64 + row] = p;
            __syncthreads();
            if (part == 0)
                wv[row] = (red[row] + red[64 + row]) + (red[128 + row] + red[192 + row]);
            __syncthreads();
        }
        if (t < 64) red[t] = v[t] * wv[t];
        __syncthreads();
        if (t < 32) {
            float s = red[t] + red[t + 32];
#pragma unroll
            for (int off = 16; off > 0; off >>= 1)
                s += __shfl_down_sync(0xffffffffu, s, off);
            if (t == 0) scal = s;
        }
        __syncthreads();
        const float lam = scal;
        if (t == 0) lamArr[k] = lam;
        if (t < 64) Vs[k * 64 + t] = v[t];
        __syncthreads();
        for (int idx = t; idx < 4096; idx += 256)
            cov[(idx >> 6) * 65 + (idx & 63)] -= lam * v[idx >> 6] * v[idx & 63];
        __syncthreads();
    }

    if (t < KEIG) invs[t] = 1.0f / sqrtf(lamArr[t] + EPSV);
    __syncthreads();
    for (int idx = t; idx < 4096; idx += 256) {
        const int c = idx >> 6, cp = idx & 63;
        float s = 0.0f;
#pragma unroll
        for (int k = 0; k < KEIG; k++)
            s += Vs[k * 64 + c] * invs[k] * Vs[k * 64 + cp];
        g_W[idx] = weight[c] * s;
    }
    __syncthreads();
    if (t < 64) {
        float s = bias[t];
        for (int cp = 0; cp < 64; cp++) s -= g_W[t * 64 + cp] * mu[cp];
        g_off[t] = s;
    }
}

// ---------------------------------------------------------------------------
// Pass 2: out = W @ x + off. 256 threads, 2 blocks/SM, double-buffered.
// Thread tile: 4 consecutive channels x 4 column-pairs. Per cp:
// 2 x-LDS.128 + 2 w-LDS.128 (broadcast) + 16 FFMA2. STG.128 outputs.
// ---------------------------------------------------------------------------
#define APPLY_SMEM (2 * CCH * RS * 4 + 4096 * 8 + 64 * 4)
#define GRAM_SMEM  (2 * CCH * RS * 4)

__global__ void __launch_bounds__(256, 2)
apply_kernel(const float* __restrict__ x, float* __restrict__ out) {
    extern __shared__ float sm[];
    float* buf0 = sm;
    float* buf1 = sm + CCH * RS;
    unsigned long long* sWp = (unsigned long long*)(sm + 2 * CCH * RS);
    float* soff = (float*)(sWp + 4096);

    const int t    = threadIdx.x;
    const int wa   = t >> 5;
    const int lane = t & 31;
    const int u    = t >> 4;     // channel group: ch0 = 4u
    const int tc   = t & 15;     // column group: m = 4tc (+64)
    const int ch0  = 4 * u;

    // prologue prefetch of tile0 (overlaps the W-table setup below)
    {
        const int tau = blockIdx.x;
        const int n = tau >> 7, m0 = (tau & 127) << 7;
        const float* base = x + (size_t)(n * CCH) * HWSZ + m0;
#pragma unroll
        for (int q = 0; q < 8; q++) {
            const int c = q * 8 + wa;
            cpa16(buf0 + c * RS + lane * 4, base + (size_t)c * HWSZ + lane * 4);
        }
    }
    CP_COMMIT;

    for (int idx = t; idx < 4096; idx += 256) {
        // sWp[cp*64 + c] = pack2(W[c][cp])
        sWp[idx] = pack2(g_W[(idx & 63) * 64 + (idx >> 6)]);
    }
    if (t < 64) soff[t] = g_off[t];

    int parity = 0;
    for (int tau = blockIdx.x; tau < NTILES; tau += G2) {
        const int taun = tau + G2;
        float* nb = parity ? buf0 : buf1;
        if (taun < NTILES) {
            const int n = taun >> 7, m0 = (taun & 127) << 7;
            const float* base = x + (size_t)(n * CCH) * HWSZ + m0;
#pragma unroll
            for (int q = 0; q < 8; q++) {
                const int c = q * 8 + wa;
                cpa16(nb + c * RS + lane * 4, base + (size_t)c * HWSZ + lane * 4);
            }
        }
        CP_COMMIT;
        CP_WAIT1;
        __syncthreads();
        const float* tb = parity ? buf1 : buf0;

        unsigned long long acc[4][4];
#pragma unroll
        for (int r = 0; r < 4; r++) {
            const unsigned long long po = pack2(soff[ch0 + r]);
#pragma unroll
            for (int p = 0; p < 4; p++) acc[r][p] = po;
        }

#pragma unroll 4
        for (int cp = 0; cp < 64; cp++) {
            const longlong2 xlo = *(const longlong2*)(tb + cp * RS + 4 * tc);
            const longlong2 xhi = *(const longlong2*)(tb + cp * RS + 64 + 4 * tc);
            const longlong2 w01 = *(const longlong2*)(sWp + cp * 64 + ch0);
            const longlong2 w23 = *(const longlong2*)(sWp + cp * 64 + ch0 + 2);
            ffma2(acc[0][0], (unsigned long long)w01.x, (unsigned long long)xlo.x);
            ffma2(acc[0][1], (unsigned long long)w01.x, (unsigned long long)xlo.y);
            ffma2(acc[0][2], (unsigned long long)w01.x, (unsigned long long)xhi.x);
            ffma2(acc[0][3], (unsigned long long)w01.x, (unsigned long long)xhi.y);
            ffma2(acc[1][0], (unsigned long long)w01.y, (unsigned long long)xlo.x);
            ffma2(acc[1][1], (unsigned long long)w01.y, (unsigned long long)xlo.y);
            ffma2(acc[1][2], (unsigned long long)w01.y, (unsigned long long)xhi.x);
            ffma2(acc[1][3], (unsigned long long)w01.y, (unsigned long long)xhi.y);
            ffma2(acc[2][0], (unsigned long long)w23.x, (unsigned long long)xlo.x);
            ffma2(acc[2][1], (unsigned long long)w23.x, (unsigned long long)xlo.y);
            ffma2(acc[2][2], (unsigned long long)w23.x, (unsigned long long)xhi.x);
            ffma2(acc[2][3], (unsigned long long)w23.x, (unsigned long long)xhi.y);
            ffma2(acc[3][0], (unsigned long long)w23.y, (unsigned long long)xlo.x);
            ffma2(acc[3][1], (unsigned long long)w23.y, (unsigned long long)xlo.y);
            ffma2(acc[3][2], (unsigned long long)w23.y, (unsigned long long)xhi.x);
            ffma2(acc[3][3], (unsigned long long)w23.y, (unsigned long long)xhi.y);
        }

        const int n = tau >> 7, m0 = (tau & 127) << 7;
        float* ob = out + (size_t)(n * CCH) * HWSZ + m0;
#pragma unroll
        for (int r = 0; r < 4; r++) {
            const int c = ch0 + r;
            ulonglong2 s0; s0.x = acc[r][0]; s0.y = acc[r][1];
            ulonglong2 s1; s1.x = acc[r][2]; s1.y = acc[r][3];
            *(ulonglong2*)(ob + (size_t)c * HWSZ + 4 * tc)      = s0;
            *(ulonglong2*)(ob + (size_t)c * HWSZ + 64 + 4 * tc) = s1;
        }
        __syncthreads();
        parity ^= 1;
    }
}

// ---------------------------------------------------------------------------
extern "C" void kernel_launch(void* const* d_in, const int* in_sizes, int n_in,
                              void* d_out, int out_size) {
    const float* x      = (const float*)d_in[0];
    const float* weight = (const float*)d_in[1];
    const float* bias   = (const float*)d_in[2];
    const float* vinit  = (const float*)d_in[3];
    float* out = (float*)d_out;

    static int configured = 0;
    cudaFuncSetAttribute(gram_kernel,
                         cudaFuncAttributeMaxDynamicSharedMemorySize, GRAM_SMEM);
    cudaFuncSetAttribute(apply_kernel,
                         cudaFuncAttributeMaxDynamicSharedMemorySize, APPLY_SMEM);
    (void)configured;

    gram_kernel<<<G1, 256, GRAM_SMEM>>>(x);
    reduce_kernel<<<65, 64>>>();
    eigen_kernel<<<1, 256>>>(weight, bias, vinit);
    apply_kernel<<<G2, 256, APPLY_SMEM>>>(x, out);
}